// round 8
// baseline (speedup 1.0000x reference)
#include <cuda_runtime.h>
#include <math.h>

#define DIM       512
#define NBLK      296          // = 2 * 148 SMs: exactly one balanced wave
#define THREADS_X 128          // float4 lanes covering DIM
#define THREADS_Y 4
#define NGRP      8            // completion hierarchy: 296 = 8 * 37
#define GRP_SZ    37

// Level-1 partials: per (block, dim-pair) float4 {P0,Q0,P1,Q1}. 296*256*16B = 1.2 MB.
__device__ float4 g_scratch[NBLK * (DIM / 2)];
// Level-2 partials: 8 * 256 * 16B = 32 KB.
__device__ float4 g_scratch2[NGRP * (DIM / 2)];
// Completion counters (zero-initialized at load; reset by final block each run).
__device__ int g_cnt_grp[NGRP];
__device__ int g_cnt_fin;

// ---------------------------------------------------------------------------
// Fused kernel: streaming column reduction + in-kernel hierarchical finish.
//
// Closed form per dim d (s = pv - pc):
//   sum_t log(2*pi*var_t)        = T*log2pi + (T-1)*log(s) + log(s + T*pc)
//   sum_t (z_t-mu_t)^2 / var_t   = (Q - pc/(s+T*pc) * P^2) / s
// with P = Sz - T*mu0, Q = Szz - 2*mu0*Sz + T*mu0^2.
// c0 = -0.5 * T * log(2pi), host double.
// ---------------------------------------------------------------------------
__global__ void __launch_bounds__(THREADS_X * THREADS_Y)
k_fused(const float* __restrict__ z,
        const float* __restrict__ var_vbl,
        const float* __restrict__ corr_vbl,
        const float* __restrict__ prior_mu,
        float* __restrict__ out,
        int T, float c0) {
    const int x   = threadIdx.x;                  // 0..127
    const int y   = threadIdx.y;                  // 0..3
    const int tid = y * THREADS_X + x;
    const int b   = blockIdx.x;

    // ---- Phase 1: streaming partial reduction -----------------------------
    // Row-groups of 4 rows (one per y). Total groups = T/4 = 16384.
    // Distribute: first 104 blocks get 56 groups, rest get 55 (16384 = 104*56 + 192*55).
    const int base_cnt = 16384 / NBLK;            // 55
    const int rem      = 16384 % NBLK;            // 104
    const int g0    = b * base_cnt + (b < rem ? b : rem);
    const int iters = base_cnt + (b < rem ? 1 : 0);

    const float4* __restrict__ zp = reinterpret_cast<const float4*>(z);

    float4 P = make_float4(0.f, 0.f, 0.f, 0.f);
    float4 Q = make_float4(0.f, 0.f, 0.f, 0.f);

    #pragma unroll 8
    for (int i = 0; i < iters; ++i) {
        const long long row = (long long)(g0 + i) * THREADS_Y + y;
        float4 v = __ldcs(&zp[row * (DIM / 4) + x]);
        P.x += v.x; P.y += v.y; P.z += v.z; P.w += v.w;
        Q.x = fmaf(v.x, v.x, Q.x);
        Q.y = fmaf(v.y, v.y, Q.y);
        Q.z = fmaf(v.z, v.z, Q.z);
        Q.w = fmaf(v.w, v.w, Q.w);
    }

    __shared__ float4 sP[THREADS_Y][THREADS_X];
    __shared__ float4 sQ[THREADS_Y][THREADS_X];
    sP[y][x] = P;
    sQ[y][x] = Q;
    __syncthreads();

    if (y == 0) {
        float4 p = sP[0][x];
        float4 q = sQ[0][x];
        #pragma unroll
        for (int j = 1; j < THREADS_Y; ++j) {
            float4 pj = sP[j][x];
            float4 qj = sQ[j][x];
            p.x += pj.x; p.y += pj.y; p.z += pj.z; p.w += pj.w;
            q.x += qj.x; q.y += qj.y; q.z += qj.z; q.w += qj.w;
        }
        float4* __restrict__ outp = &g_scratch[b * (DIM / 2) + 2 * x];
        outp[0] = make_float4(p.x, q.x, p.y, q.y);
        outp[1] = make_float4(p.z, q.z, p.w, q.w);
        __threadfence();   // partials visible before the counter bump
    }
    __syncthreads();

    // ---- Phase 2: last block of each 37-block group reduces the group -----
    __shared__ int s_flag;
    const int grp = b / GRP_SZ;                   // 0..7
    if (tid == 0) {
        int done = atomicAdd(&g_cnt_grp[grp], 1);
        s_flag = (done == GRP_SZ - 1);
    }
    __syncthreads();
    if (!s_flag) return;

    __threadfence();                               // acquire partials
    if (tid < DIM / 2) {
        const float4* __restrict__ sc = &g_scratch[grp * GRP_SZ * (DIM / 2)];
        float4 acc = make_float4(0.f, 0.f, 0.f, 0.f);
        #pragma unroll 8
        for (int r = 0; r < GRP_SZ; ++r) {
            float4 v = sc[r * (DIM / 2) + tid];
            acc.x += v.x; acc.y += v.y; acc.z += v.z; acc.w += v.w;
        }
        g_scratch2[grp * (DIM / 2) + tid] = acc;
        __threadfence();
    }
    __syncthreads();

    // ---- Phase 3: last group-leader does the final reduce + epilogue ------
    __shared__ int s_fin;
    if (tid == 0) {
        int done = atomicAdd(&g_cnt_fin, 1);
        s_fin = (done == NGRP - 1);
    }
    __syncthreads();
    if (!s_fin) return;

    __threadfence();                               // acquire level-2 partials
    __shared__ float red[DIM / 2];
    const int j = tid;                             // dim-pair 0..255
    if (j < DIM / 2) {
        float4 acc = make_float4(0.f, 0.f, 0.f, 0.f);
        #pragma unroll
        for (int g = 0; g < NGRP; ++g) {
            float4 v = g_scratch2[g * (DIM / 2) + j];
            acc.x += v.x; acc.y += v.y; acc.z += v.z; acc.w += v.w;
        }

        const float Tn = (float)T;
        float lkd_pair = 0.f;
        #pragma unroll
        for (int w = 0; w < 2; ++w) {
            const int d = 2 * j + w;
            const float Sz  = w ? acc.z : acc.x;
            const float Szz = w ? acc.w : acc.y;

            const float x1  = var_vbl[d];
            const float x2  = corr_vbl[d];
            const float mu0 = prior_mu[d];

            const float sp = (x1 > 20.0f) ? x1 : log1pf(expf(x1));
            const float pv = sp * sp;
            const float sg = 1.0f / (1.0f + expf(-x2));
            const float pc = sg * pv;
            const float s  = pv - pc;

            const float Pd = Sz - Tn * mu0;
            const float Qd = Szz - 2.0f * mu0 * Sz + Tn * mu0 * mu0;

            const float denom = s + Tn * pc;
            const float quad  = (Qd - (pc / denom) * Pd * Pd) / s;

            lkd_pair += c0 - 0.5f * ((Tn - 1.0f) * logf(s) + logf(denom) + quad);
        }
        red[j] = lkd_pair;
    }
    __syncthreads();

    #pragma unroll
    for (int off = DIM / 4; off > 0; off >>= 1) {
        if (j < off) red[j] += red[j + off];
        __syncthreads();
    }

    if (tid == 0) out[0] = red[0];

    // Reset counters for the next graph replay (all arrivals already happened:
    // g_cnt_fin reached NGRP only after every block bumped its group counter).
    if (tid < NGRP) g_cnt_grp[tid] = 0;
    if (tid == NGRP) g_cnt_fin = 0;
}

// ---------------------------------------------------------------------------
extern "C" void kernel_launch(void* const* d_in, const int* in_sizes, int n_in,
                              void* d_out, int out_size) {
    const float* z_rest   = (const float*)d_in[0];   // [T, 512]
    const float* var_vbl  = (const float*)d_in[1];   // [512]
    const float* corr_vbl = (const float*)d_in[2];   // [512]
    const float* prior_mu = (const float*)d_in[3];   // [512]
    float* out = (float*)d_out;

    const int T = in_sizes[0] / DIM;                 // 65536

    const double LOG_2PI = 1.8378770664093454835606594728112;
    const float c0 = (float)(-0.5 * (double)T * LOG_2PI);

    dim3 blk(THREADS_X, THREADS_Y);
    k_fused<<<NBLK, blk>>>(z_rest, var_vbl, corr_vbl, prior_mu, out, T, c0);
}

// round 9
// speedup vs baseline: 1.0810x; 1.0810x over previous
#include <cuda_runtime.h>
#include <math.h>

#define DIM       512
#define NBLK      296          // = 2 * 148 SMs: exactly one balanced wave
#define THREADS_X 128          // float4 lanes covering DIM
#define THREADS_Y 4
#define NGRP      8            // completion hierarchy: 296 = 8 * 37
#define GRP_SZ    37

// Level-1 partials: per (block, dim-pair) float4 {P0,Q0,P1,Q1}. 296*256*16B = 1.2 MB.
__device__ float4 g_scratch[NBLK * (DIM / 2)];
// Level-2 partials: 8 * 256 * 16B = 32 KB.
__device__ float4 g_scratch2[NGRP * (DIM / 2)];
// Completion counters (zero-initialized at load; reset by final block each run).
__device__ int g_cnt_grp[NGRP];
__device__ int g_cnt_fin;

// ---------------------------------------------------------------------------
// Fused kernel: streaming column reduction (4x batched independent loads for
// MLP) + in-kernel hierarchical finish.
//
// Closed form per dim d (s = pv - pc):
//   sum_t log(2*pi*var_t)        = T*log2pi + (T-1)*log(s) + log(s + T*pc)
//   sum_t (z_t-mu_t)^2 / var_t   = (Q - pc/(s+T*pc) * P^2) / s
// with P = Sz - T*mu0, Q = Szz - 2*mu0*Sz + T*mu0^2.
// c0 = -0.5 * T * log(2pi), host double.
// ---------------------------------------------------------------------------
__global__ void __launch_bounds__(THREADS_X * THREADS_Y)
k_fused(const float* __restrict__ z,
        const float* __restrict__ var_vbl,
        const float* __restrict__ corr_vbl,
        const float* __restrict__ prior_mu,
        float* __restrict__ out,
        int T, float c0) {
    const int x   = threadIdx.x;                  // 0..127
    const int y   = threadIdx.y;                  // 0..3
    const int tid = y * THREADS_X + x;
    const int b   = blockIdx.x;

    // ---- Phase 1: streaming partial reduction -----------------------------
    // Row-groups of 4 rows (one per y). Total groups = T/4 = 16384.
    // First 104 blocks get 56 groups, rest 55 (16384 = 104*56 + 192*55).
    const int base_cnt = 16384 / NBLK;            // 55
    const int rem      = 16384 % NBLK;            // 104
    const int g0    = b * base_cnt + (b < rem ? b : rem);
    const int iters = base_cnt + (b < rem ? 1 : 0);

    const float4* __restrict__ zp = reinterpret_cast<const float4*>(z);
    // This thread's base pointer for row-group g0, row offset y, lane x.
    const float4* __restrict__ tp =
        zp + ((long long)g0 * THREADS_Y + y) * (DIM / 4) + x;
    const int STRIDE = THREADS_Y * (DIM / 4);     // one row-group = 4 rows

    float4 P = make_float4(0.f, 0.f, 0.f, 0.f);
    float4 Q = make_float4(0.f, 0.f, 0.f, 0.f);

    int i = 0;
    // Batched: 4 independent loads in flight per thread (64 KB/SM in flight).
    for (; i + 4 <= iters; i += 4) {
        float4 v0 = __ldcs(tp + (long long)(i + 0) * STRIDE);
        float4 v1 = __ldcs(tp + (long long)(i + 1) * STRIDE);
        float4 v2 = __ldcs(tp + (long long)(i + 2) * STRIDE);
        float4 v3 = __ldcs(tp + (long long)(i + 3) * STRIDE);
        P.x += v0.x; P.y += v0.y; P.z += v0.z; P.w += v0.w;
        Q.x = fmaf(v0.x, v0.x, Q.x); Q.y = fmaf(v0.y, v0.y, Q.y);
        Q.z = fmaf(v0.z, v0.z, Q.z); Q.w = fmaf(v0.w, v0.w, Q.w);
        P.x += v1.x; P.y += v1.y; P.z += v1.z; P.w += v1.w;
        Q.x = fmaf(v1.x, v1.x, Q.x); Q.y = fmaf(v1.y, v1.y, Q.y);
        Q.z = fmaf(v1.z, v1.z, Q.z); Q.w = fmaf(v1.w, v1.w, Q.w);
        P.x += v2.x; P.y += v2.y; P.z += v2.z; P.w += v2.w;
        Q.x = fmaf(v2.x, v2.x, Q.x); Q.y = fmaf(v2.y, v2.y, Q.y);
        Q.z = fmaf(v2.z, v2.z, Q.z); Q.w = fmaf(v2.w, v2.w, Q.w);
        P.x += v3.x; P.y += v3.y; P.z += v3.z; P.w += v3.w;
        Q.x = fmaf(v3.x, v3.x, Q.x); Q.y = fmaf(v3.y, v3.y, Q.y);
        Q.z = fmaf(v3.z, v3.z, Q.z); Q.w = fmaf(v3.w, v3.w, Q.w);
    }
    for (; i < iters; ++i) {
        float4 v = __ldcs(tp + (long long)i * STRIDE);
        P.x += v.x; P.y += v.y; P.z += v.z; P.w += v.w;
        Q.x = fmaf(v.x, v.x, Q.x); Q.y = fmaf(v.y, v.y, Q.y);
        Q.z = fmaf(v.z, v.z, Q.z); Q.w = fmaf(v.w, v.w, Q.w);
    }

    __shared__ float4 sP[THREADS_Y][THREADS_X];
    __shared__ float4 sQ[THREADS_Y][THREADS_X];
    sP[y][x] = P;
    sQ[y][x] = Q;
    __syncthreads();

    if (y == 0) {
        float4 p = sP[0][x];
        float4 q = sQ[0][x];
        #pragma unroll
        for (int j = 1; j < THREADS_Y; ++j) {
            float4 pj = sP[j][x];
            float4 qj = sQ[j][x];
            p.x += pj.x; p.y += pj.y; p.z += pj.z; p.w += pj.w;
            q.x += qj.x; q.y += qj.y; q.z += qj.z; q.w += qj.w;
        }
        float4* __restrict__ outp = &g_scratch[b * (DIM / 2) + 2 * x];
        outp[0] = make_float4(p.x, q.x, p.y, q.y);
        outp[1] = make_float4(p.z, q.z, p.w, q.w);
        __threadfence();   // partials visible before the counter bump
    }
    __syncthreads();

    // ---- Phase 2: last block of each 37-block group reduces the group -----
    __shared__ int s_flag;
    const int grp = b / GRP_SZ;                   // 0..7
    if (tid == 0) {
        int done = atomicAdd(&g_cnt_grp[grp], 1);
        s_flag = (done == GRP_SZ - 1);
    }
    __syncthreads();
    if (!s_flag) return;

    __threadfence();                               // acquire partials
    if (tid < DIM / 2) {
        const float4* __restrict__ sc = &g_scratch[grp * GRP_SZ * (DIM / 2)];
        float4 acc = make_float4(0.f, 0.f, 0.f, 0.f);
        #pragma unroll 8
        for (int r = 0; r < GRP_SZ; ++r) {
            float4 v = sc[r * (DIM / 2) + tid];
            acc.x += v.x; acc.y += v.y; acc.z += v.z; acc.w += v.w;
        }
        g_scratch2[grp * (DIM / 2) + tid] = acc;
        __threadfence();
    }
    __syncthreads();

    // ---- Phase 3: last group-leader does the final reduce + epilogue ------
    __shared__ int s_fin;
    if (tid == 0) {
        int done = atomicAdd(&g_cnt_fin, 1);
        s_fin = (done == NGRP - 1);
    }
    __syncthreads();
    if (!s_fin) return;

    __threadfence();                               // acquire level-2 partials
    __shared__ float red[DIM / 2];
    const int j = tid;                             // dim-pair 0..255
    if (j < DIM / 2) {
        float4 acc = make_float4(0.f, 0.f, 0.f, 0.f);
        #pragma unroll
        for (int g = 0; g < NGRP; ++g) {
            float4 v = g_scratch2[g * (DIM / 2) + j];
            acc.x += v.x; acc.y += v.y; acc.z += v.z; acc.w += v.w;
        }

        const float Tn = (float)T;
        float lkd_pair = 0.f;
        #pragma unroll
        for (int w = 0; w < 2; ++w) {
            const int d = 2 * j + w;
            const float Sz  = w ? acc.z : acc.x;
            const float Szz = w ? acc.w : acc.y;

            const float x1  = var_vbl[d];
            const float x2  = corr_vbl[d];
            const float mu0 = prior_mu[d];

            const float sp = (x1 > 20.0f) ? x1 : log1pf(expf(x1));
            const float pv = sp * sp;
            const float sg = 1.0f / (1.0f + expf(-x2));
            const float pc = sg * pv;
            const float s  = pv - pc;

            const float Pd = Sz - Tn * mu0;
            const float Qd = Szz - 2.0f * mu0 * Sz + Tn * mu0 * mu0;

            const float denom = s + Tn * pc;
            const float quad  = (Qd - (pc / denom) * Pd * Pd) / s;

            lkd_pair += c0 - 0.5f * ((Tn - 1.0f) * logf(s) + logf(denom) + quad);
        }
        red[j] = lkd_pair;
    }
    __syncthreads();

    #pragma unroll
    for (int off = DIM / 4; off > 0; off >>= 1) {
        if (j < off) red[j] += red[j + off];
        __syncthreads();
    }

    if (tid == 0) out[0] = red[0];

    // Reset counters for the next graph replay (safe: g_cnt_fin reached NGRP
    // only after every block bumped its group counter).
    if (tid < NGRP) g_cnt_grp[tid] = 0;
    if (tid == NGRP) g_cnt_fin = 0;
}

// ---------------------------------------------------------------------------
extern "C" void kernel_launch(void* const* d_in, const int* in_sizes, int n_in,
                              void* d_out, int out_size) {
    const float* z_rest   = (const float*)d_in[0];   // [T, 512]
    const float* var_vbl  = (const float*)d_in[1];   // [512]
    const float* corr_vbl = (const float*)d_in[2];   // [512]
    const float* prior_mu = (const float*)d_in[3];   // [512]
    float* out = (float*)d_out;

    const int T = in_sizes[0] / DIM;                 // 65536

    const double LOG_2PI = 1.8378770664093454835606594728112;
    const float c0 = (float)(-0.5 * (double)T * LOG_2PI);

    dim3 blk(THREADS_X, THREADS_Y);
    k_fused<<<NBLK, blk>>>(z_rest, var_vbl, corr_vbl, prior_mu, out, T, c0);
}